// round 5
// baseline (speedup 1.0000x reference)
#include <cuda_runtime.h>

#define N_NODES 100000
#define N_EDGES 1600000
#define E_TOT   (N_EDGES + N_NODES)
#define N_GRAPHS 64
#define NEG_SLOPE 0.2f
#define NEG_BIG  -1e30f
#define SCAN_BLK 1024
#define N_SBLK   ((N_NODES + SCAN_BLK - 1) / SCAN_BLK)   // 98
#define CAP      100     // per-warp edge-slot capacity (banks conflict-free: 100%32=4)

// ---------------- scratch (device globals; no allocation) ----------------
__device__ float    g_s1[8], g_d1[8];
__device__ int      g_ei_is64, g_b_is64;
__device__ int      g_src[E_TOT];
__device__ int      g_dst[E_TOT];
__device__ int      g_batch[N_NODES];
__device__ int      g_deg[N_NODES];
__device__ int      g_incl[N_NODES];
__device__ int      g_bsum[N_SBLK];
__device__ int      g_boff[N_SBLK];
__device__ int      g_rowstart[N_NODES + 1];
__device__ int      g_cursor[N_NODES];
__device__ int      g_csr_src[E_TOT];
__device__ float    g_t1  [N_NODES * 8];
__device__ float    g_h2  [N_NODES * 128];
__device__ float    g_as2 [N_NODES * 8];
__device__ float    g_ad2 [N_NODES * 8];
__device__ float    g_sums[N_GRAPHS * 16];
__device__ float    g_cnt [N_GRAPHS];

__device__ __forceinline__ float lrelu(float v) {
    return v > 0.f ? v : NEG_SLOPE * v;
}

// packed f32x2 helpers
__device__ __forceinline__ unsigned long long pack2(float lo, float hi) {
    unsigned long long r;
    asm("mov.b64 %0, {%1, %2};" : "=l"(r) : "f"(lo), "f"(hi));
    return r;
}
__device__ __forceinline__ void unpack2(unsigned long long p, float& lo, float& hi) {
    asm("mov.b64 {%0, %1}, %2;" : "=f"(lo), "=f"(hi) : "l"(p));
}
__device__ __forceinline__ void ffma2(unsigned long long& acc,
                                      unsigned long long a,
                                      unsigned long long b) {
    asm("fma.rn.f32x2 %0, %1, %2, %0;" : "+l"(acc) : "l"(a), "l"(b));
}

// ---------------- setup kernels ----------------

__global__ void k_detect(const int* __restrict__ ei,
                         const int* __restrict__ ba) {
    __shared__ int s_e, s_b;
    if (threadIdx.x == 0) { s_e = 1; s_b = 1; }
    __syncthreads();
    int t = threadIdx.x;  // 64 threads
    int we = 2 * (t * 24999 + 13) + 1;          // < 3,200,000
    if (ei[we] != 0) atomicExch(&s_e, 0);
    int wb = (N_NODES - 1) - 2 * t;             // odd indices, in-bounds
    if (ba[wb] != 0) atomicExch(&s_b, 0);
    __syncthreads();
    if (threadIdx.x == 0) { g_ei_is64 = s_e; g_b_is64 = s_b; }
}

__global__ void k_init() {
    int i = blockIdx.x * blockDim.x + threadIdx.x;
    if (i < N_NODES) g_deg[i] = 0;
    if (i < N_GRAPHS * 16) g_sums[i] = 0.f;
    if (i < N_GRAPHS)      g_cnt[i]  = 0.f;
    if (i == 0)            g_rowstart[N_NODES] = E_TOT;
}

__global__ void k_prep(const float* __restrict__ W1,
                       const float* __restrict__ att_src1,
                       const float* __restrict__ att_dst1) {
    int t = threadIdx.x;
    if (t < 8) {
        float a = 0.f;
        for (int c = 0; c < 8; c++) a += W1[t * 8 + c] * att_src1[t * 8 + c];
        g_s1[t] = a;
    } else if (t < 16) {
        int h = t - 8;
        float a = 0.f;
        for (int c = 0; c < 8; c++) a += W1[h * 8 + c] * att_dst1[h * 8 + c];
        g_d1[h] = a;
    }
}

__global__ void k_convert(const void* __restrict__ eiv) {
    int i = blockIdx.x * blockDim.x + threadIdx.x;
    if (i >= E_TOT) return;
    int s, d;
    if (i < N_EDGES) {
        if (g_ei_is64) {
            const long long* ei = (const long long*)eiv;
            s = (int)ei[i];
            d = (int)ei[N_EDGES + i];
        } else {
            const int* ei = (const int*)eiv;
            s = ei[i];
            d = ei[N_EDGES + i];
        }
    } else {
        s = i - N_EDGES;
        d = s;
    }
    g_src[i] = s;
    g_dst[i] = d;
    atomicAdd(&g_deg[d], 1);
}

__global__ void k_convert_batch(const void* __restrict__ bav) {
    int i = blockIdx.x * blockDim.x + threadIdx.x;
    if (i >= N_NODES) return;
    if (g_b_is64) g_batch[i] = (int)((const long long*)bav)[i];
    else          g_batch[i] = ((const int*)bav)[i];
}

// ---- two-level scan ----
__global__ void k_scan1() {
    __shared__ int sh[SCAN_BLK];
    int t = threadIdx.x;
    int i = blockIdx.x * SCAN_BLK + t;
    int v = (i < N_NODES) ? g_deg[i] : 0;
    sh[t] = v;
    __syncthreads();
#pragma unroll
    for (int off = 1; off < SCAN_BLK; off <<= 1) {
        int tmp = (t >= off) ? sh[t - off] : 0;
        __syncthreads();
        sh[t] += tmp;
        __syncthreads();
    }
    if (i < N_NODES) g_incl[i] = sh[t];
    if (t == SCAN_BLK - 1) g_bsum[blockIdx.x] = sh[t];
}

__global__ void k_scan2() {
    __shared__ int sh[128];
    int t = threadIdx.x;
    int v = (t < N_SBLK) ? g_bsum[t] : 0;
    sh[t] = v;
    __syncthreads();
#pragma unroll
    for (int off = 1; off < 128; off <<= 1) {
        int tmp = (t >= off) ? sh[t - off] : 0;
        __syncthreads();
        sh[t] += tmp;
        __syncthreads();
    }
    if (t < N_SBLK) g_boff[t] = sh[t] - v;
}

__global__ void k_scan3() {
    int i = blockIdx.x * blockDim.x + threadIdx.x;
    if (i >= N_NODES) return;
    int rs = g_incl[i] - g_deg[i] + g_boff[i >> 10];
    g_rowstart[i] = rs;
    g_cursor[i]   = rs;
}

__global__ void k_scatter() {
    int i = blockIdx.x * blockDim.x + threadIdx.x;
    if (i >= E_TOT) return;
    int d = g_dst[i];
    int p = atomicAdd(&g_cursor[d], 1);
    g_csr_src[p] = g_src[i];
}

// ---- layer 1: warp per dst node, smem-staged xs, 8 exp/edge ----
__global__ void __launch_bounds__(256) k_l1(const float* __restrict__ x) {
    __shared__ float s_x[8][CAP];
    int w = (blockIdx.x * blockDim.x + threadIdx.x) >> 5;
    if (w >= N_NODES) return;
    int wl = (threadIdx.x >> 5);   // warp within block
    int lane = threadIdx.x & 31;
    int eo = lane >> 3, h = lane & 7;
    int start = g_rowstart[w], end = g_rowstart[w + 1];
    int deg = end - start;
    float cs = g_s1[h];
    float cd = g_d1[h] * x[w];

    if (deg <= CAP) {
        // stage xs with all 32 lanes
        for (int j = lane; j < deg; j += 32)
            s_x[wl][j] = x[g_csr_src[start + j]];
        __syncwarp();
        // max pass (no exp)
        float m = NEG_BIG;
        for (int i = eo; i < deg; i += 4)
            m = fmaxf(m, lrelu(fmaf(s_x[wl][i], cs, cd)));
#pragma unroll
        for (int off = 8; off <= 16; off <<= 1)
            m = fmaxf(m, __shfl_xor_sync(0xffffffffu, m, off));
        // num/den pass: one exp per (edge,head)
        float den = 0.f, num = 0.f;
        for (int i = eo; i < deg; i += 4) {
            float xs = s_x[wl][i];
            float wj = __expf(lrelu(fmaf(xs, cs, cd)) - m);
            den += wj;
            num += wj * xs;
        }
#pragma unroll
        for (int off = 8; off <= 16; off <<= 1) {
            den += __shfl_xor_sync(0xffffffffu, den, off);
            num += __shfl_xor_sync(0xffffffffu, num, off);
        }
        if (lane < 8) g_t1[w * 8 + h] = num / den;
    } else {
        // fallback: online softmax (rare/never)
        float m = NEG_BIG, den = 0.f, num = 0.f;
        for (int j = start + eo; j < end; j += 4) {
            float xs = x[g_csr_src[j]];
            float e = lrelu(fmaf(xs, cs, cd));
            float nm = fmaxf(m, e);
            float r = __expf(m - nm);
            float wj = __expf(e - nm);
            den = den * r + wj;
            num = num * r + wj * xs;
            m = nm;
        }
#pragma unroll
        for (int off = 8; off <= 16; off <<= 1) {
            float m2 = __shfl_xor_sync(0xffffffffu, m,   off);
            float d2 = __shfl_xor_sync(0xffffffffu, den, off);
            float n2 = __shfl_xor_sync(0xffffffffu, num, off);
            float nm = fmaxf(m, m2);
            float r1 = __expf(m - nm), r2 = __expf(m2 - nm);
            den = den * r1 + d2 * r2;
            num = num * r1 + n2 * r2;
            m = nm;
        }
        if (lane < 8) g_t1[w * 8 + h] = num / den;
    }
}

// ---- GEMM2 + fused elu input + fused att2 epilogue ----
__global__ void __launch_bounds__(128) k_gemm2(const float* __restrict__ W1,
                                               const float* __restrict__ b1,
                                               const float* __restrict__ W2,
                                               const float* __restrict__ att_src2,
                                               const float* __restrict__ att_dst2) {
    __shared__ float s_in[16][64];
    int t = threadIdx.x;
    int n0 = blockIdx.x * 16;
    for (int e = t; e < 1024; e += 128) {
        int nn = e >> 6, j = e & 63;
        float v = fmaf(g_t1[(n0 + nn) * 8 + (j >> 3)], W1[j], b1[j]);
        s_in[nn][j] = v > 0.f ? v : (__expf(v) - 1.f);
    }
    __syncthreads();
    int lane = t & 31;
    int ng = t >> 5;
    int c = lane * 4;
    int h = lane >> 2;          // head owning these 4 cols
    unsigned long long acc01[4], acc23[4];
#pragma unroll
    for (int i = 0; i < 4; i++) { acc01[i] = 0ull; acc23[i] = 0ull; }
    const float* w2p = &W2[c];
#pragma unroll 4
    for (int k = 0; k < 64; k++) {
        float4 wv = *reinterpret_cast<const float4*>(w2p + k * 128);
        unsigned long long s01 = pack2(s_in[ng * 4 + 0][k], s_in[ng * 4 + 1][k]);
        unsigned long long s23 = pack2(s_in[ng * 4 + 2][k], s_in[ng * 4 + 3][k]);
        unsigned long long w0 = pack2(wv.x, wv.x);
        unsigned long long w1 = pack2(wv.y, wv.y);
        unsigned long long w2 = pack2(wv.z, wv.z);
        unsigned long long w3 = pack2(wv.w, wv.w);
        ffma2(acc01[0], w0, s01); ffma2(acc23[0], w0, s23);
        ffma2(acc01[1], w1, s01); ffma2(acc23[1], w1, s23);
        ffma2(acc01[2], w2, s01); ffma2(acc23[2], w2, s23);
        ffma2(acc01[3], w3, s01); ffma2(acc23[3], w3, s23);
    }
    float4 av = *reinterpret_cast<const float4*>(&att_src2[c]);
    float4 dv = *reinterpret_cast<const float4*>(&att_dst2[c]);
    float4 row[4];
    {
        float lo[4], hi[4];
#pragma unroll
        for (int i = 0; i < 4; i++) unpack2(acc01[i], lo[i], hi[i]);
        row[0] = make_float4(lo[0], lo[1], lo[2], lo[3]);
        row[1] = make_float4(hi[0], hi[1], hi[2], hi[3]);
#pragma unroll
        for (int i = 0; i < 4; i++) unpack2(acc23[i], lo[i], hi[i]);
        row[2] = make_float4(lo[0], lo[1], lo[2], lo[3]);
        row[3] = make_float4(hi[0], hi[1], hi[2], hi[3]);
    }
    int nb = n0 + ng * 4;
#pragma unroll
    for (int r = 0; r < 4; r++) {
        *reinterpret_cast<float4*>(&g_h2[(nb + r) * 128 + c]) = row[r];
        float pa = row[r].x * av.x + row[r].y * av.y + row[r].z * av.z + row[r].w * av.w;
        float pd = row[r].x * dv.x + row[r].y * dv.y + row[r].z * dv.z + row[r].w * dv.w;
        pa += __shfl_xor_sync(0xffffffffu, pa, 1);
        pd += __shfl_xor_sync(0xffffffffu, pd, 1);
        pa += __shfl_xor_sync(0xffffffffu, pa, 2);
        pd += __shfl_xor_sync(0xffffffffu, pd, 2);
        if ((lane & 3) == 0) {
            g_as2[(nb + r) * 8 + h] = pa;
            g_ad2[(nb + r) * 8 + h] = pd;
        }
    }
}

// ---- layer 2 fused: smem-staged weights, 8 exp/edge, gather, pool ----
__global__ void __launch_bounds__(256) k_l2() {
    __shared__ float s_w[8][8][CAP];   // [warp][head][slot]
    __shared__ int   s_s[8][CAP];      // [warp][slot] src node
    int d = (blockIdx.x * blockDim.x + threadIdx.x) >> 5;
    if (d >= N_NODES) return;
    int wl = threadIdx.x >> 5;
    int lane = threadIdx.x & 31;
    int start = g_rowstart[d], end = g_rowstart[d + 1];
    int deg = end - start;
    int h = lane & 7, eo = lane >> 3;
    float ad = g_ad2[d * 8 + h];

    float ax = 0.f, ay = 0.f, az = 0.f, aw = 0.f;
    int hh = lane >> 2;
    float dh;

    if (deg <= CAP) {
        // pass 0: gather as2 once, store logits + src; max (no exp)
        float m = NEG_BIG;
        for (int i = eo; i < deg; i += 4) {
            int s = g_csr_src[start + i];
            float e = lrelu(g_as2[s * 8 + h] + ad);
            s_w[wl][h][i] = e;
            if (h == 0) s_s[wl][i] = s;
            m = fmaxf(m, e);
        }
#pragma unroll
        for (int off = 8; off <= 16; off <<= 1)
            m = fmaxf(m, __shfl_xor_sync(0xffffffffu, m, off));
        __syncwarp();
        // pass 1: weights in-place, den
        float den = 0.f;
        for (int i = eo; i < deg; i += 4) {
            float wgt = __expf(s_w[wl][h][i] - m);
            s_w[wl][h][i] = wgt;
            den += wgt;
        }
#pragma unroll
        for (int off = 8; off <= 16; off <<= 1)
            den += __shfl_xor_sync(0xffffffffu, den, off);
        dh = __shfl_sync(0xffffffffu, den, hh);
        __syncwarp();
        // pass B: gather h2 rows weighted by smem weights (no exp)
        int k = 0;
        for (; k + 1 < deg; k += 2) {
            int s0 = s_s[wl][k];
            int s1 = s_s[wl][k + 1];
            float w0 = s_w[wl][hh][k];
            float w1 = s_w[wl][hh][k + 1];
            float4 v0 = *reinterpret_cast<const float4*>(&g_h2[s0 * 128 + lane * 4]);
            float4 v1 = *reinterpret_cast<const float4*>(&g_h2[s1 * 128 + lane * 4]);
            ax += w0 * v0.x + w1 * v1.x;
            ay += w0 * v0.y + w1 * v1.y;
            az += w0 * v0.z + w1 * v1.z;
            aw += w0 * v0.w + w1 * v1.w;
        }
        if (k < deg) {
            int s0 = s_s[wl][k];
            float w0 = s_w[wl][hh][k];
            float4 v0 = *reinterpret_cast<const float4*>(&g_h2[s0 * 128 + lane * 4]);
            ax += w0 * v0.x; ay += w0 * v0.y; az += w0 * v0.z; aw += w0 * v0.w;
        }
    } else {
        // fallback: recompute path (rare/never)
        float m = NEG_BIG, den = 0.f;
        for (int j = start + eo; j < end; j += 4) {
            int s = g_csr_src[j];
            float e = lrelu(g_as2[s * 8 + h] + ad);
            float nm = fmaxf(m, e);
            den = den * __expf(m - nm) + __expf(e - nm);
            m = nm;
        }
#pragma unroll
        for (int off = 8; off <= 16; off <<= 1) {
            float m2 = __shfl_xor_sync(0xffffffffu, m,   off);
            float d2 = __shfl_xor_sync(0xffffffffu, den, off);
            float nm = fmaxf(m, m2);
            den = den * __expf(m - nm) + d2 * __expf(m2 - nm);
            m = nm;
        }
        float mh  = __shfl_sync(0xffffffffu, m,   hh);
        dh        = __shfl_sync(0xffffffffu, den, hh);
        float adh = __shfl_sync(0xffffffffu, ad,  hh);
        for (int j = start; j < end; j++) {
            int s0 = g_csr_src[j];
            float w0 = __expf(lrelu(g_as2[s0 * 8 + hh] + adh) - mh);
            float4 v0 = *reinterpret_cast<const float4*>(&g_h2[s0 * 128 + lane * 4]);
            ax += w0 * v0.x; ay += w0 * v0.y; az += w0 * v0.z; aw += w0 * v0.w;
        }
    }

    float inv = 0.125f / dh;
    ax *= inv; ay *= inv; az *= inv; aw *= inv;
#pragma unroll
    for (int off = 4; off <= 16; off <<= 1) {
        ax += __shfl_xor_sync(0xffffffffu, ax, off);
        ay += __shfl_xor_sync(0xffffffffu, ay, off);
        az += __shfl_xor_sync(0xffffffffu, az, off);
        aw += __shfl_xor_sync(0xffffffffu, aw, off);
    }
    int g = g_batch[d];
    if (lane < 4) {
        float* dst = &g_sums[g * 16 + lane * 4];
        atomicAdd(dst + 0, ax);
        atomicAdd(dst + 1, ay);
        atomicAdd(dst + 2, az);
        atomicAdd(dst + 3, aw);
    }
    if (lane == 4) atomicAdd(&g_cnt[g], 1.f);
}

// pooled = sums/cnt + b2 ; out = pooled @ Wfc + bfc
__global__ void k_final(const float* __restrict__ b2,
                        const float* __restrict__ Wfc,
                        const float* __restrict__ bfc,
                        float* __restrict__ out) {
    int g = threadIdx.x;
    if (g >= N_GRAPHS) return;
    float inv = 1.f / fmaxf(g_cnt[g], 1.f);
    float acc[4] = {bfc[0], bfc[1], bfc[2], bfc[3]};
#pragma unroll
    for (int c = 0; c < 16; c++) {
        float p = g_sums[g * 16 + c] * inv + b2[c];
#pragma unroll
        for (int o = 0; o < 4; o++) acc[o] += p * Wfc[c * 4 + o];
    }
#pragma unroll
    for (int o = 0; o < 4; o++) out[g * 4 + o] = acc[o];
}

// ---------------- launch ----------------
extern "C" void kernel_launch(void* const* d_in, const int* in_sizes, int n_in,
                              void* d_out, int out_size) {
    const float* x        = (const float*)d_in[0];
    const float* W1       = (const float*)d_in[1];
    const float* att_src1 = (const float*)d_in[2];
    const float* att_dst1 = (const float*)d_in[3];
    const float* b1       = (const float*)d_in[4];
    const float* W2       = (const float*)d_in[5];
    const float* att_src2 = (const float*)d_in[6];
    const float* att_dst2 = (const float*)d_in[7];
    const float* b2       = (const float*)d_in[8];
    const float* Wfc      = (const float*)d_in[9];
    const float* bfc      = (const float*)d_in[10];
    const void*  ei       = d_in[11];
    const void*  batch    = d_in[12];
    float* out = (float*)d_out;

    const int T = 256;
    k_detect<<<1, 64>>>((const int*)ei, (const int*)batch);
    k_init<<<(N_NODES + T - 1) / T, T>>>();
    k_prep<<<1, 32>>>(W1, att_src1, att_dst1);
    k_convert<<<(E_TOT + T - 1) / T, T>>>(ei);
    k_convert_batch<<<(N_NODES + T - 1) / T, T>>>(batch);
    k_scan1<<<N_SBLK, SCAN_BLK>>>();
    k_scan2<<<1, 128>>>();
    k_scan3<<<(N_NODES + T - 1) / T, T>>>();
    k_scatter<<<(E_TOT + T - 1) / T, T>>>();

    k_l1<<<(N_NODES * 32 + T - 1) / T, T>>>(x);
    k_gemm2<<<N_NODES / 16, 128>>>(W1, b1, W2, att_src2, att_dst2);
    k_l2<<<(N_NODES * 32 + T - 1) / T, T>>>();
    k_final<<<1, 64>>>(b2, Wfc, bfc, out);
}